// round 3
// baseline (speedup 1.0000x reference)
#include <cuda_runtime.h>

// Fused DGM network: out = DGM(x,t) with n_layers=read-from-input.
// One CTA = 32 rows. S and S*R tiles live in SMEM; the depth-invariant xt
// projections (uz/ug/ur/uh) live in registers (per-thread 2x8 tile of each).
// All GEMM accumulation uses packed fma.rn.f32x2 (FFMA2) since 3-reg FFMA is
// half-rate on sm_103a.

namespace {
constexpr int XDIM   = 100;
constexpr int XTDIM  = 101;   // x ++ t
constexpr int HIDDEN = 128;
constexpr int TM     = 32;    // rows per block
constexpr int NTHR   = 256;   // 16 row-groups x 16 col-groups, 2x8 tile each
constexpr int LDXT   = 104;   // padded xt stride
constexpr int LDS_S  = 132;   // padded S stride (avoid bank conflicts)
}

__device__ __forceinline__ unsigned long long pack2(float lo, float hi) {
    unsigned long long r;
    asm("mov.b64 %0, {%1, %2};" : "=l"(r) : "f"(lo), "f"(hi));
    return r;
}
__device__ __forceinline__ void unpack2(unsigned long long v, float& lo, float& hi) {
    asm("mov.b64 {%0, %1}, %2;" : "=f"(lo), "=f"(hi) : "l"(v));
}
__device__ __forceinline__ void fma2(unsigned long long& d, unsigned long long a,
                                     unsigned long long b) {
    asm("fma.rn.f32x2 %0, %1, %2, %0;" : "+l"(d) : "l"(a), "l"(b));
}
__device__ __forceinline__ unsigned long long add2(unsigned long long a,
                                                   unsigned long long b) {
    unsigned long long d;
    asm("add.rn.f32x2 %0, %1, %2;" : "=l"(d) : "l"(a), "l"(b));
    return d;
}

// tanh via exp: ~1e-7 abs error, 2 MUFU ops. Saturates correctly at +/-inf:
//   x -> +inf : e=inf, 2/inf = 0, result 1
//   x -> -inf : e=0,   2/1   = 2, result -1
__device__ __forceinline__ float fast_tanh(float v) {
    float e = __expf(2.0f * v);
    return 1.0f - __fdividef(2.0f, e + 1.0f);
}

// acc[2][4] (f32x2 pairs) = bias[c0..c0+7] ; acc += A[r0..r0+1][0..K) @ W[0..K)[c0..c0+7]
// A in shared (stride LDA), W row-major [K][128] in global (L1/L2-resident).
template <int K, int LDA>
__device__ __forceinline__ void gemm2x8(const float* __restrict__ sA, int r0,
                                        const float* __restrict__ W,
                                        const float* __restrict__ bias, int c0,
                                        unsigned long long acc[2][4]) {
    const ulonglong2* b2 = reinterpret_cast<const ulonglong2*>(bias + c0);
    ulonglong2 bb0 = b2[0];
    ulonglong2 bb1 = b2[1];
    acc[0][0] = bb0.x; acc[0][1] = bb0.y; acc[0][2] = bb1.x; acc[0][3] = bb1.y;
    acc[1][0] = bb0.x; acc[1][1] = bb0.y; acc[1][2] = bb1.x; acc[1][3] = bb1.y;

    const float* a0p = sA + (size_t)r0 * LDA;
    const float* a1p = a0p + LDA;
#pragma unroll 4
    for (int k = 0; k < K; ++k) {
        float a0 = a0p[k];
        float a1 = a1p[k];
        unsigned long long av0 = pack2(a0, a0);
        unsigned long long av1 = pack2(a1, a1);
        const ulonglong2* wp =
            reinterpret_cast<const ulonglong2*>(W + (size_t)k * HIDDEN + c0);
        ulonglong2 w0 = wp[0];
        ulonglong2 w1 = wp[1];
        fma2(acc[0][0], av0, w0.x); fma2(acc[0][1], av0, w0.y);
        fma2(acc[0][2], av0, w1.x); fma2(acc[0][3], av0, w1.y);
        fma2(acc[1][0], av1, w0.x); fma2(acc[1][1], av1, w0.y);
        fma2(acc[1][2], av1, w1.x); fma2(acc[1][3], av1, w1.y);
    }
}

__global__ void __launch_bounds__(NTHR) dgm_fused_kernel(
    const float* __restrict__ x, const float* __restrict__ t,
    const float* __restrict__ Sw_w, const float* __restrict__ Sw_b,
    const float* __restrict__ Uz_w, const float* __restrict__ Uz_b,
    const float* __restrict__ Wsz_w, const float* __restrict__ Wsz_b,
    const float* __restrict__ Ug_w, const float* __restrict__ Ug_b,
    const float* __restrict__ Wsg_w, const float* __restrict__ Wsg_b,
    const float* __restrict__ Ur_w, const float* __restrict__ Ur_b,
    const float* __restrict__ Wsr_w, const float* __restrict__ Wsr_b,
    const float* __restrict__ Uh_w, const float* __restrict__ Uh_b,
    const float* __restrict__ Wsh_w, const float* __restrict__ Wsh_b,
    const float* __restrict__ Wf_w, const float* __restrict__ Wf_b,
    const int* __restrict__ n_layers_p, float* __restrict__ out) {
    __shared__ float sXT[TM][LDXT];
    __shared__ float sS[TM][LDS_S];
    __shared__ float sSR[TM][LDS_S];

    const int tid = threadIdx.x;
    const int row0_g = blockIdx.x * TM;

    // ---- stage xt = [x | t | 0-pad] into shared (vectorized float4) ----
    {
        const float4* x4 = reinterpret_cast<const float4*>(x);  // row stride = 25 float4
        for (int idx = tid; idx < TM * 25; idx += NTHR) {
            int m = idx / 25;
            int q = idx - m * 25;
            float4 v = x4[(size_t)(row0_g + m) * 25 + q];
            sXT[m][q * 4 + 0] = v.x;
            sXT[m][q * 4 + 1] = v.y;
            sXT[m][q * 4 + 2] = v.z;
            sXT[m][q * 4 + 3] = v.w;
        }
        if (tid < TM) {
            sXT[tid][100] = t[row0_g + tid];
            sXT[tid][101] = 0.0f;
            sXT[tid][102] = 0.0f;
            sXT[tid][103] = 0.0f;
        }
    }
    __syncthreads();

    const int c0 = (tid & 15) * 8;   // col base, 0..120
    const int r0 = (tid >> 4) * 2;   // row base, 0..30

    unsigned long long uz[2][4], ug[2][4], ur[2][4], uh[2][4], acc[2][4];

    // ---- phase 1: S1 = tanh(xt@Sw+b); hoisted projections uz/ug/ur/uh ----
    gemm2x8<XTDIM, LDXT>(&sXT[0][0], r0, Sw_w, Sw_b, c0, acc);
#pragma unroll
    for (int i = 0; i < 2; ++i)
#pragma unroll
        for (int j = 0; j < 4; ++j) {
            float lo, hi;
            unpack2(acc[i][j], lo, hi);
            sS[r0 + i][c0 + 2 * j]     = fast_tanh(lo);
            sS[r0 + i][c0 + 2 * j + 1] = fast_tanh(hi);
        }
    gemm2x8<XTDIM, LDXT>(&sXT[0][0], r0, Uz_w, Uz_b, c0, uz);
    gemm2x8<XTDIM, LDXT>(&sXT[0][0], r0, Ug_w, Ug_b, c0, ug);
    gemm2x8<XTDIM, LDXT>(&sXT[0][0], r0, Ur_w, Ur_b, c0, ur);
    gemm2x8<XTDIM, LDXT>(&sXT[0][0], r0, Uh_w, Uh_b, c0, uh);
    __syncthreads();

    const int nl = *n_layers_p;
    float Z[2][8], G[2][8];

#pragma unroll 1
    for (int l = 1; l < nl; ++l) {
        // Z = tanh(uz + S@Wsz + bz)
        gemm2x8<HIDDEN, LDS_S>(&sS[0][0], r0, Wsz_w, Wsz_b, c0, acc);
#pragma unroll
        for (int i = 0; i < 2; ++i)
#pragma unroll
            for (int j = 0; j < 4; ++j) {
                float lo, hi;
                unpack2(add2(acc[i][j], uz[i][j]), lo, hi);
                Z[i][2 * j]     = fast_tanh(lo);
                Z[i][2 * j + 1] = fast_tanh(hi);
            }
        // G = tanh(ug + S@Wsg + bg)
        gemm2x8<HIDDEN, LDS_S>(&sS[0][0], r0, Wsg_w, Wsg_b, c0, acc);
#pragma unroll
        for (int i = 0; i < 2; ++i)
#pragma unroll
            for (int j = 0; j < 4; ++j) {
                float lo, hi;
                unpack2(add2(acc[i][j], ug[i][j]), lo, hi);
                G[i][2 * j]     = fast_tanh(lo);
                G[i][2 * j + 1] = fast_tanh(hi);
            }
        // R = tanh(ur + S@Wsr + br);  sSR = S * R
        gemm2x8<HIDDEN, LDS_S>(&sS[0][0], r0, Wsr_w, Wsr_b, c0, acc);
#pragma unroll
        for (int i = 0; i < 2; ++i)
#pragma unroll
            for (int j = 0; j < 4; ++j) {
                float lo, hi;
                unpack2(add2(acc[i][j], ur[i][j]), lo, hi);
                float rv0 = fast_tanh(lo);
                float rv1 = fast_tanh(hi);
                sSR[r0 + i][c0 + 2 * j]     = sS[r0 + i][c0 + 2 * j] * rv0;
                sSR[r0 + i][c0 + 2 * j + 1] = sS[r0 + i][c0 + 2 * j + 1] * rv1;
            }
        __syncthreads();  // sSR complete; all full-row reads of sS are done

        // H = uh + SR@Wsh + bh ;  S <- (1-G)*H + Z*S
        gemm2x8<HIDDEN, LDS_S>(&sSR[0][0], r0, Wsh_w, Wsh_b, c0, acc);
#pragma unroll
        for (int i = 0; i < 2; ++i)
#pragma unroll
            for (int j = 0; j < 4; ++j) {
                float h0, h1;
                unpack2(add2(acc[i][j], uh[i][j]), h0, h1);
                float s0 = sS[r0 + i][c0 + 2 * j];
                float s1 = sS[r0 + i][c0 + 2 * j + 1];
                float g0 = G[i][2 * j], g1 = G[i][2 * j + 1];
                sS[r0 + i][c0 + 2 * j]     = (1.0f - g0) * h0 + Z[i][2 * j] * s0;
                sS[r0 + i][c0 + 2 * j + 1] = (1.0f - g1) * h1 + Z[i][2 * j + 1] * s1;
            }
        __syncthreads();  // new S visible to next layer
    }

    // ---- final: out = S @ Wf + bf (8 threads per row, shfl-reduce) ----
    {
        const int orow = tid >> 3;  // 0..31
        const int ol   = tid & 7;   // 0..7
        float s = 0.0f;
#pragma unroll
        for (int k = 0; k < 16; ++k) {
            int kk = ol * 16 + k;
            s += sS[orow][kk] * Wf_w[kk];
        }
        s += __shfl_down_sync(0xFFFFFFFFu, s, 4, 8);
        s += __shfl_down_sync(0xFFFFFFFFu, s, 2, 8);
        s += __shfl_down_sync(0xFFFFFFFFu, s, 1, 8);
        if (ol == 0) out[row0_g + orow] = s + Wf_b[0];
    }
}

extern "C" void kernel_launch(void* const* d_in, const int* in_sizes, int n_in,
                              void* d_out, int out_size) {
    const float* x     = (const float*)d_in[0];
    const float* t     = (const float*)d_in[1];
    const float* Sw_w  = (const float*)d_in[2];
    const float* Sw_b  = (const float*)d_in[3];
    const float* Uz_w  = (const float*)d_in[4];
    const float* Uz_b  = (const float*)d_in[5];
    const float* Wsz_w = (const float*)d_in[6];
    const float* Wsz_b = (const float*)d_in[7];
    const float* Ug_w  = (const float*)d_in[8];
    const float* Ug_b  = (const float*)d_in[9];
    const float* Wsg_w = (const float*)d_in[10];
    const float* Wsg_b = (const float*)d_in[11];
    const float* Ur_w  = (const float*)d_in[12];
    const float* Ur_b  = (const float*)d_in[13];
    const float* Wsr_w = (const float*)d_in[14];
    const float* Wsr_b = (const float*)d_in[15];
    const float* Uh_w  = (const float*)d_in[16];
    const float* Uh_b  = (const float*)d_in[17];
    const float* Wsh_w = (const float*)d_in[18];
    const float* Wsh_b = (const float*)d_in[19];
    const float* Wf_w  = (const float*)d_in[20];
    const float* Wf_b  = (const float*)d_in[21];
    const int*   nlp   = (const int*)d_in[22];  // little-endian: low word ok for i32/i64
    float* out = (float*)d_out;

    const int B = in_sizes[0] / XDIM;  // 262144
    const int nblocks = B / TM;        // 8192

    dgm_fused_kernel<<<nblocks, NTHR>>>(
        x, t, Sw_w, Sw_b, Uz_w, Uz_b, Wsz_w, Wsz_b, Ug_w, Ug_b, Wsg_w, Wsg_b,
        Ur_w, Ur_b, Wsr_w, Wsr_b, Uh_w, Uh_b, Wsh_w, Wsh_b, Wf_w, Wf_b, nlp, out);
}

// round 4
// speedup vs baseline: 1.0011x; 1.0011x over previous
#include <cuda_runtime.h>

// Fused DGM network: out = DGM(x,t) with n_layers=read-from-input.
// One CTA = 32 rows. S and S*R tiles live in SMEM; the depth-invariant xt
// projections (uz/ug/ur/uh) live in registers (per-thread 2x8 tile of each).
// All GEMM accumulation uses packed fma.rn.f32x2 (FFMA2) since 3-reg FFMA is
// half-rate on sm_103a.

namespace {
constexpr int XDIM   = 100;
constexpr int XTDIM  = 101;   // x ++ t
constexpr int HIDDEN = 128;
constexpr int TM     = 32;    // rows per block
constexpr int NTHR   = 256;   // 16 row-groups x 16 col-groups, 2x8 tile each
constexpr int LDXT   = 104;   // padded xt stride
constexpr int LDS_S  = 132;   // padded S stride (avoid bank conflicts)
}

__device__ __forceinline__ unsigned long long pack2(float lo, float hi) {
    unsigned long long r;
    asm("mov.b64 %0, {%1, %2};" : "=l"(r) : "f"(lo), "f"(hi));
    return r;
}
__device__ __forceinline__ void unpack2(unsigned long long v, float& lo, float& hi) {
    asm("mov.b64 {%0, %1}, %2;" : "=f"(lo), "=f"(hi) : "l"(v));
}
__device__ __forceinline__ void fma2(unsigned long long& d, unsigned long long a,
                                     unsigned long long b) {
    asm("fma.rn.f32x2 %0, %1, %2, %0;" : "+l"(d) : "l"(a), "l"(b));
}
__device__ __forceinline__ unsigned long long add2(unsigned long long a,
                                                   unsigned long long b) {
    unsigned long long d;
    asm("add.rn.f32x2 %0, %1, %2;" : "=l"(d) : "l"(a), "l"(b));
    return d;
}

// tanh via exp: ~1e-7 abs error, 2 MUFU ops. Saturates correctly at +/-inf:
//   x -> +inf : e=inf, 2/inf = 0, result 1
//   x -> -inf : e=0,   2/1   = 2, result -1
__device__ __forceinline__ float fast_tanh(float v) {
    float e = __expf(2.0f * v);
    return 1.0f - __fdividef(2.0f, e + 1.0f);
}

// acc[2][4] (f32x2 pairs) = bias[c0..c0+7] ; acc += A[r0..r0+1][0..K) @ W[0..K)[c0..c0+7]
// A in shared (stride LDA), W row-major [K][128] in global (L1/L2-resident).
template <int K, int LDA>
__device__ __forceinline__ void gemm2x8(const float* __restrict__ sA, int r0,
                                        const float* __restrict__ W,
                                        const float* __restrict__ bias, int c0,
                                        unsigned long long acc[2][4]) {
    const ulonglong2* b2 = reinterpret_cast<const ulonglong2*>(bias + c0);
    ulonglong2 bb0 = b2[0];
    ulonglong2 bb1 = b2[1];
    acc[0][0] = bb0.x; acc[0][1] = bb0.y; acc[0][2] = bb1.x; acc[0][3] = bb1.y;
    acc[1][0] = bb0.x; acc[1][1] = bb0.y; acc[1][2] = bb1.x; acc[1][3] = bb1.y;

    const float* a0p = sA + (size_t)r0 * LDA;
    const float* a1p = a0p + LDA;
#pragma unroll 4
    for (int k = 0; k < K; ++k) {
        float a0 = a0p[k];
        float a1 = a1p[k];
        unsigned long long av0 = pack2(a0, a0);
        unsigned long long av1 = pack2(a1, a1);
        const ulonglong2* wp =
            reinterpret_cast<const ulonglong2*>(W + (size_t)k * HIDDEN + c0);
        ulonglong2 w0 = wp[0];
        ulonglong2 w1 = wp[1];
        fma2(acc[0][0], av0, w0.x); fma2(acc[0][1], av0, w0.y);
        fma2(acc[0][2], av0, w1.x); fma2(acc[0][3], av0, w1.y);
        fma2(acc[1][0], av1, w0.x); fma2(acc[1][1], av1, w0.y);
        fma2(acc[1][2], av1, w1.x); fma2(acc[1][3], av1, w1.y);
    }
}

__global__ void __launch_bounds__(NTHR) dgm_fused_kernel(
    const float* __restrict__ x, const float* __restrict__ t,
    const float* __restrict__ Sw_w, const float* __restrict__ Sw_b,
    const float* __restrict__ Uz_w, const float* __restrict__ Uz_b,
    const float* __restrict__ Wsz_w, const float* __restrict__ Wsz_b,
    const float* __restrict__ Ug_w, const float* __restrict__ Ug_b,
    const float* __restrict__ Wsg_w, const float* __restrict__ Wsg_b,
    const float* __restrict__ Ur_w, const float* __restrict__ Ur_b,
    const float* __restrict__ Wsr_w, const float* __restrict__ Wsr_b,
    const float* __restrict__ Uh_w, const float* __restrict__ Uh_b,
    const float* __restrict__ Wsh_w, const float* __restrict__ Wsh_b,
    const float* __restrict__ Wf_w, const float* __restrict__ Wf_b,
    const int* __restrict__ n_layers_p, float* __restrict__ out) {
    __shared__ float sXT[TM][LDXT];
    __shared__ float sS[TM][LDS_S];
    __shared__ float sSR[TM][LDS_S];

    const int tid = threadIdx.x;
    const int row0_g = blockIdx.x * TM;

    // ---- stage xt = [x | t | 0-pad] into shared (vectorized float4) ----
    {
        const float4* x4 = reinterpret_cast<const float4*>(x);  // row stride = 25 float4
        for (int idx = tid; idx < TM * 25; idx += NTHR) {
            int m = idx / 25;
            int q = idx - m * 25;
            float4 v = x4[(size_t)(row0_g + m) * 25 + q];
            sXT[m][q * 4 + 0] = v.x;
            sXT[m][q * 4 + 1] = v.y;
            sXT[m][q * 4 + 2] = v.z;
            sXT[m][q * 4 + 3] = v.w;
        }
        if (tid < TM) {
            sXT[tid][100] = t[row0_g + tid];
            sXT[tid][101] = 0.0f;
            sXT[tid][102] = 0.0f;
            sXT[tid][103] = 0.0f;
        }
    }
    __syncthreads();

    const int c0 = (tid & 15) * 8;   // col base, 0..120
    const int r0 = (tid >> 4) * 2;   // row base, 0..30

    unsigned long long uz[2][4], ug[2][4], ur[2][4], uh[2][4], acc[2][4];

    // ---- phase 1: S1 = tanh(xt@Sw+b); hoisted projections uz/ug/ur/uh ----
    gemm2x8<XTDIM, LDXT>(&sXT[0][0], r0, Sw_w, Sw_b, c0, acc);
#pragma unroll
    for (int i = 0; i < 2; ++i)
#pragma unroll
        for (int j = 0; j < 4; ++j) {
            float lo, hi;
            unpack2(acc[i][j], lo, hi);
            sS[r0 + i][c0 + 2 * j]     = fast_tanh(lo);
            sS[r0 + i][c0 + 2 * j + 1] = fast_tanh(hi);
        }
    gemm2x8<XTDIM, LDXT>(&sXT[0][0], r0, Uz_w, Uz_b, c0, uz);
    gemm2x8<XTDIM, LDXT>(&sXT[0][0], r0, Ug_w, Ug_b, c0, ug);
    gemm2x8<XTDIM, LDXT>(&sXT[0][0], r0, Ur_w, Ur_b, c0, ur);
    gemm2x8<XTDIM, LDXT>(&sXT[0][0], r0, Uh_w, Uh_b, c0, uh);
    __syncthreads();

    const int nl = *n_layers_p;
    float Z[2][8], G[2][8];

#pragma unroll 1
    for (int l = 1; l < nl; ++l) {
        // Z = tanh(uz + S@Wsz + bz)
        gemm2x8<HIDDEN, LDS_S>(&sS[0][0], r0, Wsz_w, Wsz_b, c0, acc);
#pragma unroll
        for (int i = 0; i < 2; ++i)
#pragma unroll
            for (int j = 0; j < 4; ++j) {
                float lo, hi;
                unpack2(add2(acc[i][j], uz[i][j]), lo, hi);
                Z[i][2 * j]     = fast_tanh(lo);
                Z[i][2 * j + 1] = fast_tanh(hi);
            }
        // G = tanh(ug + S@Wsg + bg)
        gemm2x8<HIDDEN, LDS_S>(&sS[0][0], r0, Wsg_w, Wsg_b, c0, acc);
#pragma unroll
        for (int i = 0; i < 2; ++i)
#pragma unroll
            for (int j = 0; j < 4; ++j) {
                float lo, hi;
                unpack2(add2(acc[i][j], ug[i][j]), lo, hi);
                G[i][2 * j]     = fast_tanh(lo);
                G[i][2 * j + 1] = fast_tanh(hi);
            }
        // R = tanh(ur + S@Wsr + br);  sSR = S * R
        gemm2x8<HIDDEN, LDS_S>(&sS[0][0], r0, Wsr_w, Wsr_b, c0, acc);
#pragma unroll
        for (int i = 0; i < 2; ++i)
#pragma unroll
            for (int j = 0; j < 4; ++j) {
                float lo, hi;
                unpack2(add2(acc[i][j], ur[i][j]), lo, hi);
                float rv0 = fast_tanh(lo);
                float rv1 = fast_tanh(hi);
                sSR[r0 + i][c0 + 2 * j]     = sS[r0 + i][c0 + 2 * j] * rv0;
                sSR[r0 + i][c0 + 2 * j + 1] = sS[r0 + i][c0 + 2 * j + 1] * rv1;
            }
        __syncthreads();  // sSR complete; all full-row reads of sS are done

        // H = uh + SR@Wsh + bh ;  S <- (1-G)*H + Z*S
        gemm2x8<HIDDEN, LDS_S>(&sSR[0][0], r0, Wsh_w, Wsh_b, c0, acc);
#pragma unroll
        for (int i = 0; i < 2; ++i)
#pragma unroll
            for (int j = 0; j < 4; ++j) {
                float h0, h1;
                unpack2(add2(acc[i][j], uh[i][j]), h0, h1);
                float s0 = sS[r0 + i][c0 + 2 * j];
                float s1 = sS[r0 + i][c0 + 2 * j + 1];
                float g0 = G[i][2 * j], g1 = G[i][2 * j + 1];
                sS[r0 + i][c0 + 2 * j]     = (1.0f - g0) * h0 + Z[i][2 * j] * s0;
                sS[r0 + i][c0 + 2 * j + 1] = (1.0f - g1) * h1 + Z[i][2 * j + 1] * s1;
            }
        __syncthreads();  // new S visible to next layer
    }

    // ---- final: out = S @ Wf + bf (8 threads per row, shfl-reduce) ----
    {
        const int orow = tid >> 3;  // 0..31
        const int ol   = tid & 7;   // 0..7
        float s = 0.0f;
#pragma unroll
        for (int k = 0; k < 16; ++k) {
            int kk = ol * 16 + k;
            s += sS[orow][kk] * Wf_w[kk];
        }
        s += __shfl_down_sync(0xFFFFFFFFu, s, 4, 8);
        s += __shfl_down_sync(0xFFFFFFFFu, s, 2, 8);
        s += __shfl_down_sync(0xFFFFFFFFu, s, 1, 8);
        if (ol == 0) out[row0_g + orow] = s + Wf_b[0];
    }
}

extern "C" void kernel_launch(void* const* d_in, const int* in_sizes, int n_in,
                              void* d_out, int out_size) {
    const float* x     = (const float*)d_in[0];
    const float* t     = (const float*)d_in[1];
    const float* Sw_w  = (const float*)d_in[2];
    const float* Sw_b  = (const float*)d_in[3];
    const float* Uz_w  = (const float*)d_in[4];
    const float* Uz_b  = (const float*)d_in[5];
    const float* Wsz_w = (const float*)d_in[6];
    const float* Wsz_b = (const float*)d_in[7];
    const float* Ug_w  = (const float*)d_in[8];
    const float* Ug_b  = (const float*)d_in[9];
    const float* Wsg_w = (const float*)d_in[10];
    const float* Wsg_b = (const float*)d_in[11];
    const float* Ur_w  = (const float*)d_in[12];
    const float* Ur_b  = (const float*)d_in[13];
    const float* Wsr_w = (const float*)d_in[14];
    const float* Wsr_b = (const float*)d_in[15];
    const float* Uh_w  = (const float*)d_in[16];
    const float* Uh_b  = (const float*)d_in[17];
    const float* Wsh_w = (const float*)d_in[18];
    const float* Wsh_b = (const float*)d_in[19];
    const float* Wf_w  = (const float*)d_in[20];
    const float* Wf_b  = (const float*)d_in[21];
    const int*   nlp   = (const int*)d_in[22];  // little-endian: low word ok for i32/i64
    float* out = (float*)d_out;

    const int B = in_sizes[0] / XDIM;  // 262144
    const int nblocks = B / TM;        // 8192

    dgm_fused_kernel<<<nblocks, NTHR>>>(
        x, t, Sw_w, Sw_b, Uz_w, Uz_b, Wsz_w, Wsz_b, Ug_w, Ug_b, Wsg_w, Wsg_b,
        Ur_w, Ur_b, Wsr_w, Wsr_b, Uh_w, Uh_b, Wsh_w, Wsh_b, Wf_w, Wf_b, nlp, out);
}

// round 5
// speedup vs baseline: 1.2986x; 1.2972x over previous
#include <cuda_runtime.h>

// Fused DGM network. One CTA = 32 rows. S and S*R tiles in SMEM; hoisted xt
// projections (uz/ug/ur/uh) in registers. Packed fma.rn.f32x2 accumulation.
//
// R4 changes vs R3:
//  * Warp-column ownership: each warp owns 16 distinct output columns for all
//    32 rows (c0 = warp*16 + (lane>>4)*8, r0 = (lane&15)*2). Eliminates the
//    8x cross-warp duplication of weight-row loads through L1.
//  * Odd SMEM strides (131 / 105) -> conflict-free LDS of A columns
//    (previous strides 132/104 caused 4-way / 8-way bank conflicts).

namespace {
constexpr int XDIM   = 100;
constexpr int XTDIM  = 101;   // x ++ t
constexpr int HIDDEN = 128;
constexpr int TM     = 32;    // rows per block
constexpr int NTHR   = 256;   // 8 warps; warp w owns cols [16w, 16w+16)
constexpr int LDXT   = 105;   // odd padded xt stride (conflict-free)
constexpr int LDS_S  = 131;   // odd padded S stride (conflict-free)
}

__device__ __forceinline__ unsigned long long pack2(float lo, float hi) {
    unsigned long long r;
    asm("mov.b64 %0, {%1, %2};" : "=l"(r) : "f"(lo), "f"(hi));
    return r;
}
__device__ __forceinline__ void unpack2(unsigned long long v, float& lo, float& hi) {
    asm("mov.b64 {%0, %1}, %2;" : "=f"(lo), "=f"(hi) : "l"(v));
}
__device__ __forceinline__ void fma2(unsigned long long& d, unsigned long long a,
                                     unsigned long long b) {
    asm("fma.rn.f32x2 %0, %1, %2, %0;" : "+l"(d) : "l"(a), "l"(b));
}
__device__ __forceinline__ unsigned long long add2(unsigned long long a,
                                                   unsigned long long b) {
    unsigned long long d;
    asm("add.rn.f32x2 %0, %1, %2;" : "=l"(d) : "l"(a), "l"(b));
    return d;
}

// tanh via exp: ~1e-7 abs error, saturates correctly at +/-inf.
__device__ __forceinline__ float fast_tanh(float v) {
    float e = __expf(2.0f * v);
    return 1.0f - __fdividef(2.0f, e + 1.0f);
}

// acc[2][4] (f32x2 pairs) = bias[c0..c0+8) ; acc += A[r0..r0+2)[0..K) @ W[0..K)[c0..c0+8)
// A in shared (stride LDA), W row-major [K][128] in global (L1-resident).
template <int K, int LDA>
__device__ __forceinline__ void gemm2x8(const float* __restrict__ sA, int r0,
                                        const float* __restrict__ W,
                                        const float* __restrict__ bias, int c0,
                                        unsigned long long acc[2][4]) {
    const ulonglong2* b2 = reinterpret_cast<const ulonglong2*>(bias + c0);
    ulonglong2 bb0 = b2[0];
    ulonglong2 bb1 = b2[1];
    acc[0][0] = bb0.x; acc[0][1] = bb0.y; acc[0][2] = bb1.x; acc[0][3] = bb1.y;
    acc[1][0] = bb0.x; acc[1][1] = bb0.y; acc[1][2] = bb1.x; acc[1][3] = bb1.y;

    const float* a0p = sA + (size_t)r0 * LDA;
    const float* a1p = a0p + LDA;
#pragma unroll 4
    for (int k = 0; k < K; ++k) {
        float a0 = a0p[k];
        float a1 = a1p[k];
        unsigned long long av0 = pack2(a0, a0);
        unsigned long long av1 = pack2(a1, a1);
        const ulonglong2* wp =
            reinterpret_cast<const ulonglong2*>(W + (size_t)k * HIDDEN + c0);
        ulonglong2 w0 = wp[0];
        ulonglong2 w1 = wp[1];
        fma2(acc[0][0], av0, w0.x); fma2(acc[0][1], av0, w0.y);
        fma2(acc[0][2], av0, w1.x); fma2(acc[0][3], av0, w1.y);
        fma2(acc[1][0], av1, w0.x); fma2(acc[1][1], av1, w0.y);
        fma2(acc[1][2], av1, w1.x); fma2(acc[1][3], av1, w1.y);
    }
}

__global__ void __launch_bounds__(NTHR) dgm_fused_kernel(
    const float* __restrict__ x, const float* __restrict__ t,
    const float* __restrict__ Sw_w, const float* __restrict__ Sw_b,
    const float* __restrict__ Uz_w, const float* __restrict__ Uz_b,
    const float* __restrict__ Wsz_w, const float* __restrict__ Wsz_b,
    const float* __restrict__ Ug_w, const float* __restrict__ Ug_b,
    const float* __restrict__ Wsg_w, const float* __restrict__ Wsg_b,
    const float* __restrict__ Ur_w, const float* __restrict__ Ur_b,
    const float* __restrict__ Wsr_w, const float* __restrict__ Wsr_b,
    const float* __restrict__ Uh_w, const float* __restrict__ Uh_b,
    const float* __restrict__ Wsh_w, const float* __restrict__ Wsh_b,
    const float* __restrict__ Wf_w, const float* __restrict__ Wf_b,
    const int* __restrict__ n_layers_p, float* __restrict__ out) {
    __shared__ float sXT[TM][LDXT];
    __shared__ float sS[TM][LDS_S];
    __shared__ float sSR[TM][LDS_S];

    const int tid = threadIdx.x;
    const int row0_g = blockIdx.x * TM;

    // ---- stage xt = [x | t] into shared (vectorized float4 reads) ----
    {
        const float4* x4 = reinterpret_cast<const float4*>(x);  // row stride = 25 float4
        for (int idx = tid; idx < TM * 25; idx += NTHR) {
            int m = idx / 25;
            int q = idx - m * 25;
            float4 v = x4[(size_t)(row0_g + m) * 25 + q];
            sXT[m][q * 4 + 0] = v.x;
            sXT[m][q * 4 + 1] = v.y;
            sXT[m][q * 4 + 2] = v.z;
            sXT[m][q * 4 + 3] = v.w;
        }
        if (tid < TM) sXT[tid][100] = t[row0_g + tid];
    }
    __syncthreads();

    // Warp-column ownership mapping:
    //   warp w (tid>>5) owns columns [16w, 16w+16); within the warp,
    //   lanes 0..15 take col sub-block 0, lanes 16..31 sub-block 1, and
    //   (lane&15) selects the 2-row group. Each warp's W loads touch only
    //   64 B per k (2 unique 32 B chunks, broadcast within half-warps).
    const int c0 = (tid >> 5) * 16 + ((tid & 31) >> 4) * 8;  // 0..120
    const int r0 = (tid & 15) * 2;                           // 0..30

    unsigned long long uz[2][4], ug[2][4], ur[2][4], uh[2][4], acc[2][4];

    // ---- phase 1: S1 = tanh(xt@Sw+b); hoisted projections uz/ug/ur/uh ----
    gemm2x8<XTDIM, LDXT>(&sXT[0][0], r0, Sw_w, Sw_b, c0, acc);
#pragma unroll
    for (int i = 0; i < 2; ++i)
#pragma unroll
        for (int j = 0; j < 4; ++j) {
            float lo, hi;
            unpack2(acc[i][j], lo, hi);
            sS[r0 + i][c0 + 2 * j]     = fast_tanh(lo);
            sS[r0 + i][c0 + 2 * j + 1] = fast_tanh(hi);
        }
    gemm2x8<XTDIM, LDXT>(&sXT[0][0], r0, Uz_w, Uz_b, c0, uz);
    gemm2x8<XTDIM, LDXT>(&sXT[0][0], r0, Ug_w, Ug_b, c0, ug);
    gemm2x8<XTDIM, LDXT>(&sXT[0][0], r0, Ur_w, Ur_b, c0, ur);
    gemm2x8<XTDIM, LDXT>(&sXT[0][0], r0, Uh_w, Uh_b, c0, uh);
    __syncthreads();

    const int nl = *n_layers_p;
    float Z[2][8], G[2][8];

#pragma unroll 1
    for (int l = 1; l < nl; ++l) {
        // Z = tanh(uz + S@Wsz + bz)
        gemm2x8<HIDDEN, LDS_S>(&sS[0][0], r0, Wsz_w, Wsz_b, c0, acc);
#pragma unroll
        for (int i = 0; i < 2; ++i)
#pragma unroll
            for (int j = 0; j < 4; ++j) {
                float lo, hi;
                unpack2(add2(acc[i][j], uz[i][j]), lo, hi);
                Z[i][2 * j]     = fast_tanh(lo);
                Z[i][2 * j + 1] = fast_tanh(hi);
            }
        // G = tanh(ug + S@Wsg + bg)
        gemm2x8<HIDDEN, LDS_S>(&sS[0][0], r0, Wsg_w, Wsg_b, c0, acc);
#pragma unroll
        for (int i = 0; i < 2; ++i)
#pragma unroll
            for (int j = 0; j < 4; ++j) {
                float lo, hi;
                unpack2(add2(acc[i][j], ug[i][j]), lo, hi);
                G[i][2 * j]     = fast_tanh(lo);
                G[i][2 * j + 1] = fast_tanh(hi);
            }
        // R = tanh(ur + S@Wsr + br);  sSR = S * R
        gemm2x8<HIDDEN, LDS_S>(&sS[0][0], r0, Wsr_w, Wsr_b, c0, acc);
#pragma unroll
        for (int i = 0; i < 2; ++i)
#pragma unroll
            for (int j = 0; j < 4; ++j) {
                float lo, hi;
                unpack2(add2(acc[i][j], ur[i][j]), lo, hi);
                float rv0 = fast_tanh(lo);
                float rv1 = fast_tanh(hi);
                sSR[r0 + i][c0 + 2 * j]     = sS[r0 + i][c0 + 2 * j] * rv0;
                sSR[r0 + i][c0 + 2 * j + 1] = sS[r0 + i][c0 + 2 * j + 1] * rv1;
            }
        __syncthreads();  // sSR complete; all full-row reads of sS are done

        // H = uh + SR@Wsh + bh ;  S <- (1-G)*H + Z*S
        gemm2x8<HIDDEN, LDS_S>(&sSR[0][0], r0, Wsh_w, Wsh_b, c0, acc);
#pragma unroll
        for (int i = 0; i < 2; ++i)
#pragma unroll
            for (int j = 0; j < 4; ++j) {
                float h0, h1;
                unpack2(add2(acc[i][j], uh[i][j]), h0, h1);
                float s0 = sS[r0 + i][c0 + 2 * j];
                float s1 = sS[r0 + i][c0 + 2 * j + 1];
                float g0 = G[i][2 * j], g1 = G[i][2 * j + 1];
                sS[r0 + i][c0 + 2 * j]     = (1.0f - g0) * h0 + Z[i][2 * j] * s0;
                sS[r0 + i][c0 + 2 * j + 1] = (1.0f - g1) * h1 + Z[i][2 * j + 1] * s1;
            }
        __syncthreads();  // new S visible to next layer
    }

    // ---- final: out = S @ Wf + bf (8 threads per row, shfl-reduce) ----
    {
        const int orow = tid >> 3;  // 0..31
        const int ol   = tid & 7;   // 0..7
        float s = 0.0f;
#pragma unroll
        for (int k = 0; k < 16; ++k) {
            int kk = ol * 16 + k;
            s += sS[orow][kk] * Wf_w[kk];
        }
        s += __shfl_down_sync(0xFFFFFFFFu, s, 4, 8);
        s += __shfl_down_sync(0xFFFFFFFFu, s, 2, 8);
        s += __shfl_down_sync(0xFFFFFFFFu, s, 1, 8);
        if (ol == 0) out[row0_g + orow] = s + Wf_b[0];
    }
}

extern "C" void kernel_launch(void* const* d_in, const int* in_sizes, int n_in,
                              void* d_out, int out_size) {
    const float* x     = (const float*)d_in[0];
    const float* t     = (const float*)d_in[1];
    const float* Sw_w  = (const float*)d_in[2];
    const float* Sw_b  = (const float*)d_in[3];
    const float* Uz_w  = (const float*)d_in[4];
    const float* Uz_b  = (const float*)d_in[5];
    const float* Wsz_w = (const float*)d_in[6];
    const float* Wsz_b = (const float*)d_in[7];
    const float* Ug_w  = (const float*)d_in[8];
    const float* Ug_b  = (const float*)d_in[9];
    const float* Wsg_w = (const float*)d_in[10];
    const float* Wsg_b = (const float*)d_in[11];
    const float* Ur_w  = (const float*)d_in[12];
    const float* Ur_b  = (const float*)d_in[13];
    const float* Wsr_w = (const float*)d_in[14];
    const float* Wsr_b = (const float*)d_in[15];
    const float* Uh_w  = (const float*)d_in[16];
    const float* Uh_b  = (const float*)d_in[17];
    const float* Wsh_w = (const float*)d_in[18];
    const float* Wsh_b = (const float*)d_in[19];
    const float* Wf_w  = (const float*)d_in[20];
    const float* Wf_b  = (const float*)d_in[21];
    const int*   nlp   = (const int*)d_in[22];
    float* out = (float*)d_out;

    const int B = in_sizes[0] / XDIM;  // 262144
    const int nblocks = B / TM;        // 8192

    dgm_fused_kernel<<<nblocks, NTHR>>>(
        x, t, Sw_w, Sw_b, Uz_w, Uz_b, Wsz_w, Wsz_b, Ug_w, Ug_b, Wsg_w, Wsg_b,
        Ur_w, Ur_b, Wsr_w, Wsr_b, Uh_w, Uh_b, Wsh_w, Wsh_b, Wf_w, Wf_b, nlp, out);
}

// round 7
// speedup vs baseline: 2.6315x; 2.0264x over previous
#include <cuda_runtime.h>

// Fused DGM network. One CTA = 32 rows, 256 threads, per-thread 2x8 tile.
//
// R6: transposed SMEM activation tiles ([col][row], row-stride 32 floats).
//  * Fixes R5's misaligned-address crash: float2 A loads are now
//    {A[r0][k], A[r0+1][k]} at sAT[k*32 + r0], always 8B-aligned (r0 even).
//  * Conflict-free: half-warp lanes r0=0,2,..,30 cover all 32 banks once.
//  * One LDS.64 per k per warp (was 2 scalar LDS in R4).
//  * Kept from R5: u-projections in SMEM (register relief),
//    __launch_bounds__(256,2) + dynamic SMEM -> 2 CTAs/SM (16 warps).

namespace {
constexpr int XDIM   = 100;
constexpr int XTDIM  = 101;   // x ++ t
constexpr int HIDDEN = 128;
constexpr int TM     = 32;    // rows per block
constexpr int NTHR   = 256;   // 8 warps; warp w owns cols [16w, 16w+16)

// dynamic smem partition (bytes); activation tiles are transposed [col][row]
constexpr int OFF_U      = 0;                           // 4*8*256 ull = 65536
constexpr int OFF_S      = OFF_U + 4 * 8 * NTHR * 8;    // 65536
constexpr int OFF_SR     = OFF_S + HIDDEN * TM * 4;     // +16384 = 81920
constexpr int OFF_XT     = OFF_SR + HIDDEN * TM * 4;    // +16384 = 98304
constexpr int SMEM_TOTAL = OFF_XT + XTDIM * TM * 4;     // +12928 = 111232
}

__device__ __forceinline__ unsigned long long pack2(float lo, float hi) {
    unsigned long long r;
    asm("mov.b64 %0, {%1, %2};" : "=l"(r) : "f"(lo), "f"(hi));
    return r;
}
__device__ __forceinline__ void unpack2(unsigned long long v, float& lo, float& hi) {
    asm("mov.b64 {%0, %1}, %2;" : "=f"(lo), "=f"(hi) : "l"(v));
}
__device__ __forceinline__ void fma2(unsigned long long& d, unsigned long long a,
                                     unsigned long long b) {
    asm("fma.rn.f32x2 %0, %1, %2, %0;" : "+l"(d) : "l"(a), "l"(b));
}
__device__ __forceinline__ unsigned long long add2(unsigned long long a,
                                                   unsigned long long b) {
    unsigned long long d;
    asm("add.rn.f32x2 %0, %1, %2;" : "=l"(d) : "l"(a), "l"(b));
    return d;
}

// tanh via exp: ~1e-7 abs error, saturates correctly at +/-inf.
__device__ __forceinline__ float fast_tanh(float v) {
    float e = __expf(2.0f * v);
    return 1.0f - __fdividef(2.0f, e + 1.0f);
}

// acc[2][4] = bias[c0..c0+8) + A[r0..r0+2)[0..K) @ W[0..K)[c0..c0+8)
// A transposed in shared: sAT[k*32 + row]. One LDS.64 per k yields
// {A[r0][k], A[r0+1][k]}. W row-major [K][128] in global (L1-resident).
template <int K>
__device__ __forceinline__ void gemmT2x8(const float* __restrict__ sAT, int r0,
                                         const float* __restrict__ W,
                                         const float* __restrict__ bias, int c0,
                                         unsigned long long acc[2][4]) {
    const ulonglong2* b2 = reinterpret_cast<const ulonglong2*>(bias + c0);
    ulonglong2 bb0 = b2[0];
    ulonglong2 bb1 = b2[1];
    acc[0][0] = bb0.x; acc[0][1] = bb0.y; acc[0][2] = bb1.x; acc[0][3] = bb1.y;
    acc[1][0] = bb0.x; acc[1][1] = bb0.y; acc[1][2] = bb1.x; acc[1][3] = bb1.y;

    const float2* ap = reinterpret_cast<const float2*>(sAT + r0);  // + k*16 per k
    const char* wrow = reinterpret_cast<const char*>(W + c0);

#pragma unroll 4
    for (int k = 0; k < K; ++k) {
        float2 a = ap[(size_t)k * 16];  // a.x = row r0, a.y = row r0+1, col k
        const ulonglong2* wp =
            reinterpret_cast<const ulonglong2*>(wrow + (size_t)k * (HIDDEN * 4));
        ulonglong2 w0 = wp[0];
        ulonglong2 w1 = wp[1];
        unsigned long long av0 = pack2(a.x, a.x);
        unsigned long long av1 = pack2(a.y, a.y);
        fma2(acc[0][0], av0, w0.x); fma2(acc[0][1], av0, w0.y);
        fma2(acc[0][2], av0, w1.x); fma2(acc[0][3], av0, w1.y);
        fma2(acc[1][0], av1, w0.x); fma2(acc[1][1], av1, w0.y);
        fma2(acc[1][2], av1, w1.x); fma2(acc[1][3], av1, w1.y);
    }
}

__global__ void __launch_bounds__(NTHR, 2) dgm_fused_kernel(
    const float* __restrict__ x, const float* __restrict__ t,
    const float* __restrict__ Sw_w, const float* __restrict__ Sw_b,
    const float* __restrict__ Uz_w, const float* __restrict__ Uz_b,
    const float* __restrict__ Wsz_w, const float* __restrict__ Wsz_b,
    const float* __restrict__ Ug_w, const float* __restrict__ Ug_b,
    const float* __restrict__ Wsg_w, const float* __restrict__ Wsg_b,
    const float* __restrict__ Ur_w, const float* __restrict__ Ur_b,
    const float* __restrict__ Wsr_w, const float* __restrict__ Wsr_b,
    const float* __restrict__ Uh_w, const float* __restrict__ Uh_b,
    const float* __restrict__ Wsh_w, const float* __restrict__ Wsh_b,
    const float* __restrict__ Wf_w, const float* __restrict__ Wf_b,
    const int* __restrict__ n_layers_p, float* __restrict__ out) {
    extern __shared__ char smem[];
    unsigned long long* uS = reinterpret_cast<unsigned long long*>(smem + OFF_U);
    float* sS  = reinterpret_cast<float*>(smem + OFF_S);   // [128][32]
    float* sSR = reinterpret_cast<float*>(smem + OFF_SR);  // [128][32]
    float* sXT = reinterpret_cast<float*>(smem + OFF_XT);  // [101][32]

    const int tid = threadIdx.x;
    const int row0_g = blockIdx.x * TM;

    // ---- stage xt (transposed): sXT[k*32 + m] = xt[m][k] ----
    {
        const float4* x4 = reinterpret_cast<const float4*>(x);  // row = 25 float4
        // lane-distinct rows (m = idx&31) -> conflict-free SMEM writes
        for (int idx = tid; idx < TM * 25; idx += NTHR) {
            int m = idx & 31;
            int q = idx >> 5;  // 0..24
            float4 v = x4[(size_t)(row0_g + m) * 25 + q];
            sXT[(q * 4 + 0) * 32 + m] = v.x;
            sXT[(q * 4 + 1) * 32 + m] = v.y;
            sXT[(q * 4 + 2) * 32 + m] = v.z;
            sXT[(q * 4 + 3) * 32 + m] = v.w;
        }
        if (tid < TM) sXT[100 * 32 + tid] = t[row0_g + tid];
    }
    __syncthreads();

    // Warp-column ownership: warp w owns cols [16w,16w+16); lanes 0..15 take
    // col sub-block 0, lanes 16..31 sub-block 1; (lane&15) picks the row pair.
    const int c0 = (tid >> 5) * 16 + ((tid & 31) >> 4) * 8;  // 0..120
    const int r0 = (tid & 15) * 2;                           // 0..30

    unsigned long long acc[2][4];

    // ---- phase 1: S1 = tanh(xt@Sw+b); u-projections -> SMEM ----
    gemmT2x8<XTDIM>(sXT, r0, Sw_w, Sw_b, c0, acc);
#pragma unroll
    for (int j = 0; j < 4; ++j) {
        float l0, h0, l1, h1;
        unpack2(acc[0][j], l0, h0);  // row r0:   cols 2j, 2j+1
        unpack2(acc[1][j], l1, h1);  // row r0+1: cols 2j, 2j+1
        *reinterpret_cast<float2*>(sS + (c0 + 2 * j) * 32 + r0) =
            make_float2(fast_tanh(l0), fast_tanh(l1));
        *reinterpret_cast<float2*>(sS + (c0 + 2 * j + 1) * 32 + r0) =
            make_float2(fast_tanh(h0), fast_tanh(h1));
    }
    // uS layout: plane p (z,g,r,h), slot (i*4+j), thread tid.
    gemmT2x8<XTDIM>(sXT, r0, Uz_w, Uz_b, c0, acc);
#pragma unroll
    for (int i = 0; i < 2; ++i)
#pragma unroll
        for (int j = 0; j < 4; ++j) uS[(0 * 8 + i * 4 + j) * NTHR + tid] = acc[i][j];
    gemmT2x8<XTDIM>(sXT, r0, Ug_w, Ug_b, c0, acc);
#pragma unroll
    for (int i = 0; i < 2; ++i)
#pragma unroll
        for (int j = 0; j < 4; ++j) uS[(1 * 8 + i * 4 + j) * NTHR + tid] = acc[i][j];
    gemmT2x8<XTDIM>(sXT, r0, Ur_w, Ur_b, c0, acc);
#pragma unroll
    for (int i = 0; i < 2; ++i)
#pragma unroll
        for (int j = 0; j < 4; ++j) uS[(2 * 8 + i * 4 + j) * NTHR + tid] = acc[i][j];
    gemmT2x8<XTDIM>(sXT, r0, Uh_w, Uh_b, c0, acc);
#pragma unroll
    for (int i = 0; i < 2; ++i)
#pragma unroll
        for (int j = 0; j < 4; ++j) uS[(3 * 8 + i * 4 + j) * NTHR + tid] = acc[i][j];
    __syncthreads();

    const int nl = *n_layers_p;
    float Z[2][8], G[2][8];

#pragma unroll 1
    for (int l = 1; l < nl; ++l) {
        // Z = tanh(uz + S@Wsz + bz)
        gemmT2x8<HIDDEN>(sS, r0, Wsz_w, Wsz_b, c0, acc);
#pragma unroll
        for (int i = 0; i < 2; ++i)
#pragma unroll
            for (int j = 0; j < 4; ++j) {
                float lo, hi;
                unpack2(add2(acc[i][j], uS[(0 * 8 + i * 4 + j) * NTHR + tid]), lo, hi);
                Z[i][2 * j]     = fast_tanh(lo);
                Z[i][2 * j + 1] = fast_tanh(hi);
            }
        // G = tanh(ug + S@Wsg + bg)
        gemmT2x8<HIDDEN>(sS, r0, Wsg_w, Wsg_b, c0, acc);
#pragma unroll
        for (int i = 0; i < 2; ++i)
#pragma unroll
            for (int j = 0; j < 4; ++j) {
                float lo, hi;
                unpack2(add2(acc[i][j], uS[(1 * 8 + i * 4 + j) * NTHR + tid]), lo, hi);
                G[i][2 * j]     = fast_tanh(lo);
                G[i][2 * j + 1] = fast_tanh(hi);
            }
        // R = tanh(ur + S@Wsr + br);  sSR = S * R
        gemmT2x8<HIDDEN>(sS, r0, Wsr_w, Wsr_b, c0, acc);
#pragma unroll
        for (int j = 0; j < 4; ++j) {
            float l0, h0, l1, h1;
            unpack2(add2(acc[0][j], uS[(2 * 8 + 0 * 4 + j) * NTHR + tid]), l0, h0);
            unpack2(add2(acc[1][j], uS[(2 * 8 + 1 * 4 + j) * NTHR + tid]), l1, h1);
            int ca = (c0 + 2 * j) * 32 + r0;
            int cb = (c0 + 2 * j + 1) * 32 + r0;
            float2 sa = *reinterpret_cast<const float2*>(sS + ca);
            float2 sb = *reinterpret_cast<const float2*>(sS + cb);
            *reinterpret_cast<float2*>(sSR + ca) =
                make_float2(sa.x * fast_tanh(l0), sa.y * fast_tanh(l1));
            *reinterpret_cast<float2*>(sSR + cb) =
                make_float2(sb.x * fast_tanh(h0), sb.y * fast_tanh(h1));
        }
        __syncthreads();  // sSR complete; all full-column reads of sS done

        // H = uh + SR@Wsh + bh ;  S <- (1-G)*H + Z*S
        gemmT2x8<HIDDEN>(sSR, r0, Wsh_w, Wsh_b, c0, acc);
#pragma unroll
        for (int j = 0; j < 4; ++j) {
            float l0, h0, l1, h1;
            unpack2(add2(acc[0][j], uS[(3 * 8 + 0 * 4 + j) * NTHR + tid]), l0, h0);
            unpack2(add2(acc[1][j], uS[(3 * 8 + 1 * 4 + j) * NTHR + tid]), l1, h1);
            int ca = (c0 + 2 * j) * 32 + r0;
            int cb = (c0 + 2 * j + 1) * 32 + r0;
            float2 sa = *reinterpret_cast<const float2*>(sS + ca);
            float2 sb = *reinterpret_cast<const float2*>(sS + cb);
            // col 2j:   rows (r0, r0+1) -> (l0, l1); col 2j+1 -> (h0, h1)
            float za = Z[0][2 * j], zb = Z[1][2 * j];
            float ga = G[0][2 * j], gb = G[1][2 * j];
            *reinterpret_cast<float2*>(sS + ca) =
                make_float2((1.0f - ga) * l0 + za * sa.x,
                            (1.0f - gb) * l1 + zb * sa.y);
            za = Z[0][2 * j + 1]; zb = Z[1][2 * j + 1];
            ga = G[0][2 * j + 1]; gb = G[1][2 * j + 1];
            *reinterpret_cast<float2*>(sS + cb) =
                make_float2((1.0f - ga) * h0 + za * sb.x,
                            (1.0f - gb) * h1 + zb * sb.y);
        }
        __syncthreads();  // new S visible to next layer
    }

    // ---- final: out = S @ Wf + bf (8 threads per row, shfl-reduce) ----
    {
        const int orow = tid >> 3;  // 0..31
        const int ol   = tid & 7;   // 0..7
        float s = 0.0f;
#pragma unroll
        for (int k = 0; k < 16; ++k) {
            int kk = ol * 16 + k;
            s += sS[kk * 32 + orow] * Wf_w[kk];
        }
        s += __shfl_down_sync(0xFFFFFFFFu, s, 4, 8);
        s += __shfl_down_sync(0xFFFFFFFFu, s, 2, 8);
        s += __shfl_down_sync(0xFFFFFFFFu, s, 1, 8);
        if (ol == 0) out[row0_g + orow] = s + Wf_b[0];
    }
}

extern "C" void kernel_launch(void* const* d_in, const int* in_sizes, int n_in,
                              void* d_out, int out_size) {
    const float* x     = (const float*)d_in[0];
    const float* t     = (const float*)d_in[1];
    const float* Sw_w  = (const float*)d_in[2];
    const float* Sw_b  = (const float*)d_in[3];
    const float* Uz_w  = (const float*)d_in[4];
    const float* Uz_b  = (const float*)d_in[5];
    const float* Wsz_w = (const float*)d_in[6];
    const float* Wsz_b = (const float*)d_in[7];
    const float* Ug_w  = (const float*)d_in[8];
    const float* Ug_b  = (const float*)d_in[9];
    const float* Wsg_w = (const float*)d_in[10];
    const float* Wsg_b = (const float*)d_in[11];
    const float* Ur_w  = (const float*)d_in[12];
    const float* Ur_b  = (const float*)d_in[13];
    const float* Wsr_w = (const float*)d_in[14];
    const float* Wsr_b = (const float*)d_in[15];
    const float* Uh_w  = (const float*)d_in[16];
    const float* Uh_b  = (const float*)d_in[17];
    const float* Wsh_w = (const float*)d_in[18];
    const float* Wsh_b = (const float*)d_in[19];
    const float* Wf_w  = (const float*)d_in[20];
    const float* Wf_b  = (const float*)d_in[21];
    const int*   nlp   = (const int*)d_in[22];
    float* out = (float*)d_out;

    const int B = in_sizes[0] / XDIM;  // 262144
    const int nblocks = B / TM;        // 8192

    static bool attr_set = false;
    if (!attr_set) {
        cudaFuncSetAttribute(dgm_fused_kernel,
                             cudaFuncAttributeMaxDynamicSharedMemorySize, SMEM_TOTAL);
        attr_set = true;
    }
    dgm_fused_kernel<<<nblocks, NTHR, SMEM_TOTAL>>>(
        x, t, Sw_w, Sw_b, Uz_w, Uz_b, Wsz_w, Wsz_b, Ug_w, Ug_b, Wsg_w, Wsg_b,
        Ur_w, Ur_b, Wsr_w, Wsr_b, Uh_w, Uh_b, Wsh_w, Wsh_b, Wf_w, Wf_b, nlp, out);
}